// round 8
// baseline (speedup 1.0000x reference)
#include <cuda_runtime.h>
#include <cstdint>

#define N_NODES 50000
#define N_EDGES 800000
#define NCHUNK  ((N_NODES + 255) / 256) // 196

// ---------------------------------------------------------------------------
// scratch (__device__ globals; no allocation allowed)
// ---------------------------------------------------------------------------
__device__ float g_bufA[(size_t)N_NODES * 128];
__device__ float g_bufB[(size_t)N_NODES * 128];
__device__ float g_inv [N_NODES];
__device__ int   g_degi[N_NODES];
__device__ int   g_cursor[N_NODES];
__device__ int   g_off [N_NODES];
__device__ int   g_csr [N_EDGES];
__device__ int   g_chunksum[256];
__device__ int   g_chunkpre[256];
__device__ unsigned g_cnt;
__device__ volatile unsigned g_gen;

// ---------------------------------------------------------------------------
// grid-wide barrier
// ---------------------------------------------------------------------------
__device__ __forceinline__ void gbar(unsigned nb) {
    __syncthreads();
    if (threadIdx.x == 0) {
        __threadfence();
        unsigned my = g_gen;
        if (atomicAdd(&g_cnt, 1u) == nb - 1u) {
            g_cnt = 0u;
            __threadfence();
            g_gen = my + 1u;
        } else {
            while (g_gen == my) __nanosleep(32);
        }
        __threadfence();
    }
    __syncthreads();
}

// block-wide exclusive scan of one int per thread (256 threads)
__device__ __forceinline__ int block_exscan256(int v) {
    __shared__ int ws[8];
    const int t = threadIdx.x, lane = t & 31, wid = t >> 5;
    int s = v;
#pragma unroll
    for (int d = 1; d < 32; d <<= 1) {
        int u = __shfl_up_sync(0xFFFFFFFFu, s, d);
        if (lane >= d) s += u;
    }
    __syncthreads();
    if (lane == 31) ws[wid] = s;
    __syncthreads();
    int wpre = 0;
#pragma unroll
    for (int k = 0; k < 8; k++) if (k < wid) wpre += ws[k];
    return s - v + wpre;
}

// ---------------------------------------------------------------------------
// gather helper: warp-cooperative mean+self for NPW nodes -> sIn
// ---------------------------------------------------------------------------
template <int F_IN, int BN>
__device__ __forceinline__ void gather_group(const float* __restrict__ x,
                                             int node0, float* sIn) {
    constexpr int NPW = BN / 8;
    constexpr int VPL = F_IN / 64;
    const int t    = threadIdx.x;
    const int lane = t & 31;
    const int w    = t >> 5;
    const int sub  = lane >> 4;
    const int cl   = lane & 15;

    for (int s = 0; s < NPW; s++) {
        const int nl = w * NPW + s;
        const int n  = node0 + nl;
        if (n >= N_NODES) break;
        const int beg = g_off[n] + g_chunkpre[n >> 8];
        const int dg  = g_degi[n];

        float4 acc[VPL];
#pragma unroll
        for (int v = 0; v < VPL; v++) acc[v] = make_float4(0.f, 0.f, 0.f, 0.f);

        int j = 0;
#pragma unroll 4
        for (; j + 2 <= dg; j += 2) {
            int e = __ldg(&g_csr[beg + j + sub]);
            const float4* r = reinterpret_cast<const float4*>(x + (size_t)e * F_IN) + cl * VPL;
#pragma unroll
            for (int v = 0; v < VPL; v++) {
                float4 a = r[v];
                acc[v].x += a.x; acc[v].y += a.y; acc[v].z += a.z; acc[v].w += a.w;
            }
        }
        if (j < dg && sub == 0) {
            int e = __ldg(&g_csr[beg + j]);
            const float4* r = reinterpret_cast<const float4*>(x + (size_t)e * F_IN) + cl * VPL;
#pragma unroll
            for (int v = 0; v < VPL; v++) {
                float4 a = r[v];
                acc[v].x += a.x; acc[v].y += a.y; acc[v].z += a.z; acc[v].w += a.w;
            }
        }
#pragma unroll
        for (int v = 0; v < VPL; v++) {
            acc[v].x += __shfl_xor_sync(0xFFFFFFFFu, acc[v].x, 16);
            acc[v].y += __shfl_xor_sync(0xFFFFFFFFu, acc[v].y, 16);
            acc[v].z += __shfl_xor_sync(0xFFFFFFFFu, acc[v].z, 16);
            acc[v].w += __shfl_xor_sync(0xFFFFFFFFu, acc[v].w, 16);
        }
        if (sub == 0) {
            const float inv = g_inv[n];
            const float4* self = reinterpret_cast<const float4*>(x + (size_t)n * F_IN) + cl * VPL;
#pragma unroll
            for (int v = 0; v < VPL; v++) {
                float4 sv = self[v];
                float4 o;
                o.x = acc[v].x * inv + sv.x;
                o.y = acc[v].y * inv + sv.y;
                o.z = acc[v].z * inv + sv.z;
                o.w = acc[v].w * inv + sv.w;
                reinterpret_cast<float4*>(sIn + (size_t)nl * F_IN)[cl * VPL + v] = o;
            }
        }
    }
}

// ---------------------------------------------------------------------------
// layer phase (layers 1 & 2): tile 4 neurons x 8 nodes, BN = 64
// ---------------------------------------------------------------------------
template <int F_IN, int F_OUT>
__device__ __forceinline__ void layer_phase8(const float* __restrict__ x,
                                             const float* __restrict__ W,
                                             const float* __restrict__ b,
                                             float* __restrict__ out,
                                             unsigned nb, float* sm) {
    constexpr int NQ  = F_OUT / 4;            // 32
    constexpr int BN  = (256 / NQ) * 8;       // 64
    constexpr int NG  = (N_NODES + BN - 1) / BN;

    float* sWt = sm;                           // F_IN * F_OUT (transposed)
    float* sIn = sm + F_IN * F_OUT;            // BN * F_IN

    const int t = threadIdx.x;
    __syncthreads();
    for (int i = t; i < F_IN * F_OUT; i += 256) {
        int r = i % F_OUT;                     // neuron
        int c = i / F_OUT;                     // k
        sWt[i] = __ldg(&W[r * F_IN + c]);
    }
    const int nq = t % NQ;
    const int mo = t / NQ;                     // node-oct index
    const float4 bv = __ldg(reinterpret_cast<const float4*>(b) + nq);
    __syncthreads();

    for (int g = blockIdx.x; g < NG; g += nb) {
        const int node0 = g * BN;
        gather_group<F_IN, BN>(x, node0, sIn);
        __syncthreads();

        float acc[8][4];
#pragma unroll
        for (int i = 0; i < 8; i++) {
            acc[i][0] = bv.x; acc[i][1] = bv.y; acc[i][2] = bv.z; acc[i][3] = bv.w;
        }
        const float4* wt4 = reinterpret_cast<const float4*>(sWt);
        for (int k0 = 0; k0 < F_IN; k0 += 4) {
            float4 wv[4];
#pragma unroll
            for (int j = 0; j < 4; j++) wv[j] = wt4[(size_t)(k0 + j) * NQ + nq];
#pragma unroll
            for (int i = 0; i < 8; i++) {
                float4 v = *reinterpret_cast<const float4*>(sIn + (size_t)(mo * 8 + i) * F_IN + k0);
                acc[i][0] += v.x * wv[0].x + v.y * wv[1].x + v.z * wv[2].x + v.w * wv[3].x;
                acc[i][1] += v.x * wv[0].y + v.y * wv[1].y + v.z * wv[2].y + v.w * wv[3].y;
                acc[i][2] += v.x * wv[0].z + v.y * wv[1].z + v.z * wv[2].z + v.w * wv[3].z;
                acc[i][3] += v.x * wv[0].w + v.y * wv[1].w + v.z * wv[2].w + v.w * wv[3].w;
            }
        }
#pragma unroll
        for (int i = 0; i < 8; i++) {
            int n = node0 + mo * 8 + i;
            if (n < N_NODES) {
                float4 o;
                o.x = fmaxf(acc[i][0], 0.f);
                o.y = fmaxf(acc[i][1], 0.f);
                o.z = fmaxf(acc[i][2], 0.f);
                o.w = fmaxf(acc[i][3], 0.f);
                *reinterpret_cast<float4*>(out + (size_t)n * F_OUT + nq * 4) = o;
            }
        }
        __syncthreads();
    }
}

// ---------------------------------------------------------------------------
// layer 3 (128->64, 4x4 tile, BN=64) fused with heads
// out layout: [emb 50000*64 | next 50000*64 | cls 50000*10]
// ---------------------------------------------------------------------------
__device__ __forceinline__ void layer3_heads(const float* __restrict__ x,
                                             const float* __restrict__ W3,
                                             const float* __restrict__ b3,
                                             const float* __restrict__ Wp,
                                             const float* __restrict__ bp,
                                             const float* __restrict__ Wc,
                                             const float* __restrict__ bc,
                                             float* __restrict__ out,
                                             unsigned nb, float* sm) {
    constexpr int F_IN = 128, F_OUT = 64;
    constexpr int NQ = 16, BN = 64;            // 4x4 tile: 16 nq x 16 mq
    constexpr int NG = (N_NODES + BN - 1) / BN;
    constexpr int NH = 74, WP = 68;

    float* sWt = sm;                            // 128*64
    float* sIn = sWt + F_IN * F_OUT;            // 64*128
    float* sH  = sIn + BN * F_IN;               // 64*64
    float* sWh = sH + BN * F_OUT;               // 74*68
    float* sB  = sWh + NH * WP;                 // 80

    const int t = threadIdx.x;
    __syncthreads();
    for (int i = t; i < F_IN * F_OUT; i += 256) {
        int r = i % F_OUT;
        int c = i / F_OUT;
        sWt[i] = __ldg(&W3[r * F_IN + c]);
    }
    for (int i = t; i < 64 * 64; i += 256) sWh[(i / 64) * WP + (i % 64)] = Wp[i];
    for (int i = t; i < 10 * 64; i += 256) sWh[(64 + i / 64) * WP + (i % 64)] = Wc[i];
    if (t < 64) sB[t] = bp[t];
    else if (t < NH) sB[t] = bc[t - 64];

    const int nq = t % NQ;
    const int mq = t / NQ;
    const float4 bv = __ldg(reinterpret_cast<const float4*>(b3) + nq);
    const int sub = t >> 7;
    const int tt  = t & 127;
    __syncthreads();

    for (int g = blockIdx.x; g < NG; g += nb) {
        const int node0 = g * BN;
        gather_group<F_IN, BN>(x, node0, sIn);
        __syncthreads();

        // GEMM 4x4
        float acc[4][4];
#pragma unroll
        for (int i = 0; i < 4; i++) {
            acc[i][0] = bv.x; acc[i][1] = bv.y; acc[i][2] = bv.z; acc[i][3] = bv.w;
        }
        const float4* wt4 = reinterpret_cast<const float4*>(sWt);
        for (int k0 = 0; k0 < F_IN; k0 += 4) {
            float4 wv[4];
#pragma unroll
            for (int j = 0; j < 4; j++) wv[j] = wt4[(size_t)(k0 + j) * NQ + nq];
#pragma unroll
            for (int i = 0; i < 4; i++) {
                float4 v = *reinterpret_cast<const float4*>(sIn + (size_t)(mq * 4 + i) * F_IN + k0);
                acc[i][0] += v.x * wv[0].x + v.y * wv[1].x + v.z * wv[2].x + v.w * wv[3].x;
                acc[i][1] += v.x * wv[0].y + v.y * wv[1].y + v.z * wv[2].y + v.w * wv[3].y;
                acc[i][2] += v.x * wv[0].z + v.y * wv[1].z + v.z * wv[2].z + v.w * wv[3].z;
                acc[i][3] += v.x * wv[0].w + v.y * wv[1].w + v.z * wv[2].w + v.w * wv[3].w;
            }
        }
        // relu -> sH + embeddings output
#pragma unroll
        for (int i = 0; i < 4; i++) {
            float4 o;
            o.x = fmaxf(acc[i][0], 0.f);
            o.y = fmaxf(acc[i][1], 0.f);
            o.z = fmaxf(acc[i][2], 0.f);
            o.w = fmaxf(acc[i][3], 0.f);
            int nl = mq * 4 + i;
            *reinterpret_cast<float4*>(sH + (size_t)nl * F_OUT + nq * 4) = o;
            int n = node0 + nl;
            if (n < N_NODES)
                *reinterpret_cast<float4*>(out + (size_t)n * F_OUT + nq * 4) = o;
        }
        __syncthreads();

        // heads: 8 chunks of 8 nodes
        if (tt < NH) {
            const float4* w4 = reinterpret_cast<const float4*>(sWh + tt * WP);
            const float bias = sB[tt];
            for (int c8 = 0; c8 < 8; c8++) {
                float a2[4];
#pragma unroll
                for (int bn = 0; bn < 4; bn++) a2[bn] = bias;
#pragma unroll
                for (int k4 = 0; k4 < 16; k4++) {
                    float4 w = w4[k4];
#pragma unroll
                    for (int bn = 0; bn < 4; bn++) {
                        float4 v = *reinterpret_cast<const float4*>(
                            sH + (size_t)(c8 * 8 + sub * 4 + bn) * F_OUT + k4 * 4);
                        a2[bn] += w.x * v.x + w.y * v.y + w.z * v.z + w.w * v.w;
                    }
                }
#pragma unroll
                for (int bn = 0; bn < 4; bn++) {
                    int n = node0 + c8 * 8 + sub * 4 + bn;
                    if (n < N_NODES) {
                        if (tt < 64)
                            out[(size_t)N_NODES * 64 + (size_t)n * 64 + tt] = a2[bn];
                        else
                            out[(size_t)N_NODES * 128 + (size_t)n * 10 + (tt - 64)] = a2[bn];
                    }
                }
            }
        }
        __syncthreads();
    }
}

// ---------------------------------------------------------------------------
// the one kernel
// ---------------------------------------------------------------------------
__global__ void __launch_bounds__(256, 2)
k_mega(const float* __restrict__ x,
       const int* __restrict__ src, const int* __restrict__ dst,
       const float* __restrict__ W1, const float* __restrict__ b1,
       const float* __restrict__ W2, const float* __restrict__ b2,
       const float* __restrict__ W3, const float* __restrict__ b3,
       const float* __restrict__ Wp, const float* __restrict__ bp,
       const float* __restrict__ Wc, const float* __restrict__ bc,
       float* __restrict__ out) {
    extern __shared__ float sm[];
    const unsigned nb = gridDim.x;
    const int t = threadIdx.x;
    const int gtid = blockIdx.x * 256 + t;
    const int gstride = nb * 256;

    // P0: zero
    for (int i = gtid; i < N_NODES; i += gstride) { g_degi[i] = 0; g_cursor[i] = 0; }
    gbar(nb);
    // P1: count
    for (int e = gtid; e < N_EDGES; e += gstride) atomicAdd(&g_degi[dst[e]], 1);
    gbar(nb);
    // P2a: per-chunk exclusive scans + inverse degree
    for (int c = blockIdx.x; c < NCHUNK; c += nb) {
        int i = c * 256 + t;
        int d = (i < N_NODES) ? g_degi[i] : 0;
        int ex = block_exscan256(d);
        if (i < N_NODES) {
            g_off[i] = ex;
            g_inv[i] = 1.0f / fmaxf((float)d, 1.0f);
        }
        if (t == 255) g_chunksum[c] = ex + d;
    }
    gbar(nb);
    // P2b: scan chunk sums (block 0)
    if (blockIdx.x == 0) {
        int v = (t < NCHUNK) ? g_chunksum[t] : 0;
        int ex = block_exscan256(v);
        if (t < NCHUNK) g_chunkpre[t] = ex;
    }
    gbar(nb);
    // P3: fill CSR (offsets finalized on the fly via chunkpre)
    for (int e = gtid; e < N_EDGES; e += gstride) {
        int d = dst[e];
        int pos = atomicAdd(&g_cursor[d], 1);
        g_csr[g_off[d] + g_chunkpre[d >> 8] + pos] = src[e];
    }
    gbar(nb);
    // P4-P6: layers (+heads fused into layer3)
    layer_phase8<64, 128>(x,      W1, b1, g_bufA, nb, sm);
    gbar(nb);
    layer_phase8<128, 128>(g_bufA, W2, b2, g_bufB, nb, sm);
    gbar(nb);
    layer3_heads(g_bufB, W3, b3, Wp, bp, Wc, bc, out, nb, sm);
}

// ---------------------------------------------------------------------------
extern "C" void kernel_launch(void* const* d_in, const int* in_sizes, int n_in,
                              void* d_out, int out_size) {
    const float* x  = (const float*)d_in[0];
    const int*   ei = (const int*)d_in[1];
    const int* src = ei;
    const int* dst = ei + N_EDGES;
    const float* W1 = (const float*)d_in[2];
    const float* b1 = (const float*)d_in[3];
    const float* W2 = (const float*)d_in[4];
    const float* b2 = (const float*)d_in[5];
    const float* W3 = (const float*)d_in[6];
    const float* b3 = (const float*)d_in[7];
    const float* Wp = (const float*)d_in[8];
    const float* bp = (const float*)d_in[9];
    const float* Wc = (const float*)d_in[10];
    const float* bc = (const float*)d_in[11];
    float* out = (float*)d_out;

    // smem: max over phases
    //   layer2:       128*128*4 + 64*128*4              = 98304
    //   layer3+heads: 128*64*4 + 64*128*4 + 64*64*4 + 74*68*4 + 80*4 = 102368
    constexpr int SMEM = 128 * 64 * 4 + 64 * 128 * 4 + 64 * 64 * 4 + 74 * 68 * 4 + 80 * 4;

    static int grid = 0;
    if (grid == 0) {
        cudaFuncSetAttribute(k_mega, cudaFuncAttributeMaxDynamicSharedMemorySize, SMEM);
        int dev = 0, sms = 0, occ = 0;
        cudaGetDevice(&dev);
        cudaDeviceGetAttribute(&sms, cudaDevAttrMultiProcessorCount, dev);
        cudaOccupancyMaxActiveBlocksPerMultiprocessor(&occ, k_mega, 256, SMEM);
        if (occ < 1) occ = 1;
        grid = sms * occ;
    }

    k_mega<<<grid, 256, SMEM>>>(x, src, dst, W1, b1, W2, b2, W3, b3,
                                Wp, bp, Wc, bc, out);
}

// round 9
// speedup vs baseline: 1.0160x; 1.0160x over previous
#include <cuda_runtime.h>
#include <cstdint>

#define N_NODES 50000
#define N_EDGES 800000
#define NCHUNK  ((N_NODES + 255) / 256) // 196

// ---------------------------------------------------------------------------
// scratch (__device__ globals; no allocation allowed)
// ---------------------------------------------------------------------------
__device__ float g_bufA[(size_t)N_NODES * 128];
__device__ float g_bufB[(size_t)N_NODES * 128];
__device__ float g_inv [N_NODES];
__device__ int   g_degi[N_NODES];
__device__ int   g_cursor[N_NODES];
__device__ int   g_off [N_NODES];
__device__ int   g_csr [N_EDGES];
__device__ int   g_chunksum[256];
__device__ int   g_chunkpre[256];
__device__ unsigned g_cnt;
__device__ volatile unsigned g_gen;

// ---------------------------------------------------------------------------
// grid-wide barrier
// ---------------------------------------------------------------------------
__device__ __forceinline__ void gbar(unsigned nb) {
    __syncthreads();
    if (threadIdx.x == 0) {
        __threadfence();
        unsigned my = g_gen;
        if (atomicAdd(&g_cnt, 1u) == nb - 1u) {
            g_cnt = 0u;
            __threadfence();
            g_gen = my + 1u;
        } else {
            while (g_gen == my) __nanosleep(32);
        }
        __threadfence();
    }
    __syncthreads();
}

// block-wide exclusive scan of one int per thread (256 threads)
__device__ __forceinline__ int block_exscan256(int v) {
    __shared__ int ws[8];
    const int t = threadIdx.x, lane = t & 31, wid = t >> 5;
    int s = v;
#pragma unroll
    for (int d = 1; d < 32; d <<= 1) {
        int u = __shfl_up_sync(0xFFFFFFFFu, s, d);
        if (lane >= d) s += u;
    }
    __syncthreads();
    if (lane == 31) ws[wid] = s;
    __syncthreads();
    int wpre = 0;
#pragma unroll
    for (int k = 0; k < 8; k++) if (k < wid) wpre += ws[k];
    return s - v + wpre;
}

// ---------------------------------------------------------------------------
// pure gather phase: h[n] = mean-gather(x) + x[n], one warp per node,
// grid-stride over nodes. 16 lanes cover a row; sub selects 1 of 2 edges.
// ---------------------------------------------------------------------------
template <int F>
__device__ __forceinline__ void gather_phase(const float* __restrict__ x,
                                             float* __restrict__ h,
                                             unsigned nb) {
    constexpr int VPL = F / 64;                // float4s per 16-lane slice
    const int t     = threadIdx.x;
    const int lane  = t & 31;
    const int sub   = lane >> 4;
    const int cl    = lane & 15;
    const int gw    = blockIdx.x * 8 + (t >> 5);
    const int nwarp = nb * 8;

    for (int n = gw; n < N_NODES; n += nwarp) {
        const int beg = g_off[n] + g_chunkpre[n >> 8];
        const int dg  = g_degi[n];

        float4 acc[VPL];
#pragma unroll
        for (int v = 0; v < VPL; v++) acc[v] = make_float4(0.f, 0.f, 0.f, 0.f);

        int j = 0;
#pragma unroll 4
        for (; j + 2 <= dg; j += 2) {
            int e = __ldg(&g_csr[beg + j + sub]);
            const float4* r = reinterpret_cast<const float4*>(x + (size_t)e * F) + cl * VPL;
#pragma unroll
            for (int v = 0; v < VPL; v++) {
                float4 a = r[v];
                acc[v].x += a.x; acc[v].y += a.y; acc[v].z += a.z; acc[v].w += a.w;
            }
        }
        if (j < dg && sub == 0) {
            int e = __ldg(&g_csr[beg + j]);
            const float4* r = reinterpret_cast<const float4*>(x + (size_t)e * F) + cl * VPL;
#pragma unroll
            for (int v = 0; v < VPL; v++) {
                float4 a = r[v];
                acc[v].x += a.x; acc[v].y += a.y; acc[v].z += a.z; acc[v].w += a.w;
            }
        }
#pragma unroll
        for (int v = 0; v < VPL; v++) {
            acc[v].x += __shfl_xor_sync(0xFFFFFFFFu, acc[v].x, 16);
            acc[v].y += __shfl_xor_sync(0xFFFFFFFFu, acc[v].y, 16);
            acc[v].z += __shfl_xor_sync(0xFFFFFFFFu, acc[v].z, 16);
            acc[v].w += __shfl_xor_sync(0xFFFFFFFFu, acc[v].w, 16);
        }
        if (sub == 0) {
            const float inv = g_inv[n];
            const float4* self = reinterpret_cast<const float4*>(x + (size_t)n * F) + cl * VPL;
#pragma unroll
            for (int v = 0; v < VPL; v++) {
                float4 sv = self[v];
                float4 o;
                o.x = acc[v].x * inv + sv.x;
                o.y = acc[v].y * inv + sv.y;
                o.z = acc[v].z * inv + sv.z;
                o.w = acc[v].w * inv + sv.w;
                reinterpret_cast<float4*>(h + (size_t)n * F)[cl * VPL + v] = o;
            }
        }
    }
}

// ---------------------------------------------------------------------------
// pure GEMM phase: y[n] = relu(h[n] @ W^T + b)
// W^T in smem; input rows via warp-uniform broadcast LDG (no sIn smem).
// Thread tile: 4 neurons x 4 nodes. NQ = F_OUT/4, MQ = 256/NQ, BN = 4*MQ.
// ---------------------------------------------------------------------------
template <int F_IN, int F_OUT>
__device__ __forceinline__ void gemm_phase(const float* __restrict__ h,
                                           const float* __restrict__ W,
                                           const float* __restrict__ b,
                                           float* __restrict__ y,
                                           unsigned nb, float* sm) {
    constexpr int NQ = F_OUT / 4;
    constexpr int MQ = 256 / NQ;
    constexpr int BN = MQ * 4;
    constexpr int NG = (N_NODES + BN - 1) / BN;

    float* sWt = sm;                            // F_IN * F_OUT (transposed)
    const int t = threadIdx.x;
    __syncthreads();
    for (int i = t; i < F_IN * F_OUT; i += 256) {
        int r = i % F_OUT;                      // neuron
        int c = i / F_OUT;                      // k
        sWt[i] = __ldg(&W[r * F_IN + c]);
    }
    const int nq = t % NQ;
    const int mq = t / NQ;
    const float4 bv = __ldg(reinterpret_cast<const float4*>(b) + nq);
    const float4* wt4 = reinterpret_cast<const float4*>(sWt);
    __syncthreads();

    for (int g = blockIdx.x; g < NG; g += nb) {
        const int node0 = g * BN;
        int rows[4];
#pragma unroll
        for (int i = 0; i < 4; i++) {
            int n = node0 + mq * 4 + i;
            rows[i] = (n < N_NODES) ? n : 0;    // clamp for safe loads
        }

        float acc[4][4];
#pragma unroll
        for (int i = 0; i < 4; i++) {
            acc[i][0] = bv.x; acc[i][1] = bv.y; acc[i][2] = bv.z; acc[i][3] = bv.w;
        }
#pragma unroll 4
        for (int k0 = 0; k0 < F_IN; k0 += 4) {
            float4 wv[4];
#pragma unroll
            for (int j = 0; j < 4; j++) wv[j] = wt4[(size_t)(k0 + j) * NQ + nq];
#pragma unroll
            for (int i = 0; i < 4; i++) {
                float4 v = __ldg(reinterpret_cast<const float4*>(
                    h + (size_t)rows[i] * F_IN + k0));
                acc[i][0] += v.x * wv[0].x + v.y * wv[1].x + v.z * wv[2].x + v.w * wv[3].x;
                acc[i][1] += v.x * wv[0].y + v.y * wv[1].y + v.z * wv[2].y + v.w * wv[3].y;
                acc[i][2] += v.x * wv[0].z + v.y * wv[1].z + v.z * wv[2].z + v.w * wv[3].z;
                acc[i][3] += v.x * wv[0].w + v.y * wv[1].w + v.z * wv[2].w + v.w * wv[3].w;
            }
        }
#pragma unroll
        for (int i = 0; i < 4; i++) {
            int n = node0 + mq * 4 + i;
            if (n < N_NODES) {
                float4 o;
                o.x = fmaxf(acc[i][0], 0.f);
                o.y = fmaxf(acc[i][1], 0.f);
                o.z = fmaxf(acc[i][2], 0.f);
                o.w = fmaxf(acc[i][3], 0.f);
                *reinterpret_cast<float4*>(y + (size_t)n * F_OUT + nq * 4) = o;
            }
        }
    }
}

// ---------------------------------------------------------------------------
// heads phase: next_event(64) + classes(10); embeddings already in out.
// ---------------------------------------------------------------------------
__device__ __forceinline__ void heads_phase(const float* __restrict__ emb,
                                            const float* __restrict__ Wp,
                                            const float* __restrict__ bp,
                                            const float* __restrict__ Wc,
                                            const float* __restrict__ bc,
                                            float* __restrict__ out,
                                            unsigned nb, float* sm) {
    constexpr int F = 64, NH = 74, WP = F + 4, NG8 = N_NODES / 8;
    float* sW  = sm;
    float* sB  = sm + NH * WP;
    float* sIn = sB + 128;

    const int t = threadIdx.x;
    __syncthreads();
    for (int i = t; i < 64 * F; i += 256) sW[(i / F) * WP + (i % F)] = Wp[i];
    for (int i = t; i < 10 * F; i += 256) sW[(64 + i / F) * WP + (i % F)] = Wc[i];
    if (t < 64) sB[t] = bp[t];
    else if (t < NH) sB[t] = bc[t - 64];
    __syncthreads();

    const int sub = t >> 7;
    const int tt  = t & 127;

    for (int g = blockIdx.x; g < NG8; g += nb) {
        const int node0 = g * 8;
        for (int i = t; i < 8 * F; i += 256) sIn[i] = emb[(size_t)node0 * F + i];
        __syncthreads();

        if (tt < NH) {
            float acc[4];
#pragma unroll
            for (int bn = 0; bn < 4; bn++) acc[bn] = sB[tt];
            const float4* w4 = reinterpret_cast<const float4*>(sW + tt * WP);
#pragma unroll
            for (int k4 = 0; k4 < F / 4; k4++) {
                float4 w = w4[k4];
#pragma unroll
                for (int bn = 0; bn < 4; bn++) {
                    float4 v = reinterpret_cast<const float4*>(sIn + (sub * 4 + bn) * F)[k4];
                    acc[bn] += w.x * v.x + w.y * v.y + w.z * v.z + w.w * v.w;
                }
            }
#pragma unroll
            for (int bn = 0; bn < 4; bn++) {
                int n = node0 + sub * 4 + bn;
                if (tt < 64)
                    out[(size_t)N_NODES * 64 + (size_t)n * 64 + tt] = acc[bn];
                else
                    out[(size_t)N_NODES * 128 + (size_t)n * 10 + (tt - 64)] = acc[bn];
            }
        }
        __syncthreads();
    }
}

// ---------------------------------------------------------------------------
// the one kernel
// ---------------------------------------------------------------------------
__global__ void __launch_bounds__(256, 3)
k_mega(const float* __restrict__ x,
       const int* __restrict__ src, const int* __restrict__ dst,
       const float* __restrict__ W1, const float* __restrict__ b1,
       const float* __restrict__ W2, const float* __restrict__ b2,
       const float* __restrict__ W3, const float* __restrict__ b3,
       const float* __restrict__ Wp, const float* __restrict__ bp,
       const float* __restrict__ Wc, const float* __restrict__ bc,
       float* __restrict__ out) {
    extern __shared__ float sm[];
    const unsigned nb = gridDim.x;
    const int t = threadIdx.x;
    const int gtid = blockIdx.x * 256 + t;
    const int gstride = nb * 256;

    // P0: zero
    for (int i = gtid; i < N_NODES; i += gstride) { g_degi[i] = 0; g_cursor[i] = 0; }
    gbar(nb);
    // P1: count
    for (int e = gtid; e < N_EDGES; e += gstride) atomicAdd(&g_degi[dst[e]], 1);
    gbar(nb);
    // P2a: per-chunk exclusive scans + inverse degree
    for (int c = blockIdx.x; c < NCHUNK; c += nb) {
        int i = c * 256 + t;
        int d = (i < N_NODES) ? g_degi[i] : 0;
        int ex = block_exscan256(d);
        if (i < N_NODES) {
            g_off[i] = ex;
            g_inv[i] = 1.0f / fmaxf((float)d, 1.0f);
        }
        if (t == 255) g_chunksum[c] = ex + d;
    }
    gbar(nb);
    // P2b: scan chunk sums (block 0)
    if (blockIdx.x == 0) {
        int v = (t < NCHUNK) ? g_chunksum[t] : 0;
        int ex = block_exscan256(v);
        if (t < NCHUNK) g_chunkpre[t] = ex;
    }
    gbar(nb);
    // P3: fill CSR
    for (int e = gtid; e < N_EDGES; e += gstride) {
        int d = dst[e];
        int pos = atomicAdd(&g_cursor[d], 1);
        g_csr[g_off[d] + g_chunkpre[d >> 8] + pos] = src[e];
    }
    gbar(nb);

    // layer 1
    gather_phase<64>(x, g_bufB, nb);
    gbar(nb);
    gemm_phase<64, 128>(g_bufB, W1, b1, g_bufA, nb, sm);
    gbar(nb);
    // layer 2
    gather_phase<128>(g_bufA, g_bufB, nb);
    gbar(nb);
    gemm_phase<128, 128>(g_bufB, W2, b2, g_bufA, nb, sm);
    gbar(nb);
    // layer 3 (embeddings straight to out)
    gather_phase<128>(g_bufA, g_bufB, nb);
    gbar(nb);
    gemm_phase<128, 64>(g_bufB, W3, b3, out, nb, sm);
    gbar(nb);
    // heads (read embeddings from out)
    heads_phase(out, Wp, bp, Wc, bc, out, nb, sm);
}

// ---------------------------------------------------------------------------
extern "C" void kernel_launch(void* const* d_in, const int* in_sizes, int n_in,
                              void* d_out, int out_size) {
    const float* x  = (const float*)d_in[0];
    const int*   ei = (const int*)d_in[1];
    const int* src = ei;
    const int* dst = ei + N_EDGES;
    const float* W1 = (const float*)d_in[2];
    const float* b1 = (const float*)d_in[3];
    const float* W2 = (const float*)d_in[4];
    const float* b2 = (const float*)d_in[5];
    const float* W3 = (const float*)d_in[6];
    const float* b3 = (const float*)d_in[7];
    const float* Wp = (const float*)d_in[8];
    const float* bp = (const float*)d_in[9];
    const float* Wc = (const float*)d_in[10];
    const float* bc = (const float*)d_in[11];
    float* out = (float*)d_out;

    // smem: max phase = GEMM2 W tile = 128*128*4 = 65536
    constexpr int SMEM = 128 * 128 * 4;

    static int grid = 0;
    if (grid == 0) {
        cudaFuncSetAttribute(k_mega, cudaFuncAttributeMaxDynamicSharedMemorySize, SMEM);
        int dev = 0, sms = 0, occ = 0;
        cudaGetDevice(&dev);
        cudaDeviceGetAttribute(&sms, cudaDevAttrMultiProcessorCount, dev);
        cudaOccupancyMaxActiveBlocksPerMultiprocessor(&occ, k_mega, 256, SMEM);
        if (occ < 1) occ = 1;
        grid = sms * occ;
    }

    k_mega<<<grid, 256, SMEM>>>(x, src, dst, W1, b1, W2, b2, W3, b3,
                                Wp, bp, Wc, bc, out);
}

// round 10
// speedup vs baseline: 1.0483x; 1.0319x over previous
#include <cuda_runtime.h>
#include <cstdint>

#define N_NODES 50000
#define N_EDGES 800000
#define NCHUNK  ((N_NODES + 255) / 256) // 196

// ---------------------------------------------------------------------------
// scratch (__device__ globals; no allocation allowed)
// ---------------------------------------------------------------------------
__device__ float g_bufA[(size_t)N_NODES * 128];
__device__ float g_bufB[(size_t)N_NODES * 128];
__device__ float g_inv [N_NODES];
__device__ int   g_degi[N_NODES];
__device__ int   g_cursor[N_NODES];
__device__ int   g_off [N_NODES];
__device__ int   g_csr [N_EDGES];
__device__ int   g_chunksum[256];
__device__ int   g_chunkpre[256];
__device__ unsigned g_cnt;
__device__ volatile unsigned g_gen;

// ---------------------------------------------------------------------------
// packed f32x2 helpers (Blackwell FFMA2 via PTX)
// ---------------------------------------------------------------------------
__device__ __forceinline__ unsigned long long pk2(float lo, float hi) {
    unsigned long long r;
    asm("mov.b64 %0, {%1, %2};" : "=l"(r) : "f"(lo), "f"(hi));
    return r;
}
__device__ __forceinline__ void fma2(unsigned long long& d,
                                     unsigned long long a, unsigned long long b) {
    asm("fma.rn.f32x2 %0, %1, %2, %0;" : "+l"(d) : "l"(a), "l"(b));
}
__device__ __forceinline__ float2 upk2(unsigned long long v) {
    float2 f;
    asm("mov.b64 {%0, %1}, %2;" : "=f"(f.x), "=f"(f.y) : "l"(v));
    return f;
}

// ---------------------------------------------------------------------------
// grid-wide barrier
// ---------------------------------------------------------------------------
__device__ __forceinline__ void gbar(unsigned nb) {
    __syncthreads();
    if (threadIdx.x == 0) {
        __threadfence();
        unsigned my = g_gen;
        if (atomicAdd(&g_cnt, 1u) == nb - 1u) {
            g_cnt = 0u;
            __threadfence();
            g_gen = my + 1u;
        } else {
            while (g_gen == my) __nanosleep(32);
        }
        __threadfence();
    }
    __syncthreads();
}

// block-wide exclusive scan of one int per thread (256 threads)
__device__ __forceinline__ int block_exscan256(int v) {
    __shared__ int ws[8];
    const int t = threadIdx.x, lane = t & 31, wid = t >> 5;
    int s = v;
#pragma unroll
    for (int d = 1; d < 32; d <<= 1) {
        int u = __shfl_up_sync(0xFFFFFFFFu, s, d);
        if (lane >= d) s += u;
    }
    __syncthreads();
    if (lane == 31) ws[wid] = s;
    __syncthreads();
    int wpre = 0;
#pragma unroll
    for (int k = 0; k < 8; k++) if (k < wid) wpre += ws[k];
    return s - v + wpre;
}

// ---------------------------------------------------------------------------
// pure gather phase: h[n] = mean-gather(x) + x[n], one warp per node
// ---------------------------------------------------------------------------
template <int F>
__device__ __forceinline__ void gather_phase(const float* __restrict__ x,
                                             float* __restrict__ h,
                                             unsigned nb) {
    constexpr int VPL = F / 64;
    const int t     = threadIdx.x;
    const int lane  = t & 31;
    const int sub   = lane >> 4;
    const int cl    = lane & 15;
    const int gw    = blockIdx.x * 8 + (t >> 5);
    const int nwarp = nb * 8;

    for (int n = gw; n < N_NODES; n += nwarp) {
        const int beg = g_off[n] + g_chunkpre[n >> 8];
        const int dg  = g_degi[n];

        float4 acc[VPL];
#pragma unroll
        for (int v = 0; v < VPL; v++) acc[v] = make_float4(0.f, 0.f, 0.f, 0.f);

        int j = 0;
#pragma unroll 4
        for (; j + 2 <= dg; j += 2) {
            int e = __ldg(&g_csr[beg + j + sub]);
            const float4* r = reinterpret_cast<const float4*>(x + (size_t)e * F) + cl * VPL;
#pragma unroll
            for (int v = 0; v < VPL; v++) {
                float4 a = r[v];
                acc[v].x += a.x; acc[v].y += a.y; acc[v].z += a.z; acc[v].w += a.w;
            }
        }
        if (j < dg && sub == 0) {
            int e = __ldg(&g_csr[beg + j]);
            const float4* r = reinterpret_cast<const float4*>(x + (size_t)e * F) + cl * VPL;
#pragma unroll
            for (int v = 0; v < VPL; v++) {
                float4 a = r[v];
                acc[v].x += a.x; acc[v].y += a.y; acc[v].z += a.z; acc[v].w += a.w;
            }
        }
#pragma unroll
        for (int v = 0; v < VPL; v++) {
            acc[v].x += __shfl_xor_sync(0xFFFFFFFFu, acc[v].x, 16);
            acc[v].y += __shfl_xor_sync(0xFFFFFFFFu, acc[v].y, 16);
            acc[v].z += __shfl_xor_sync(0xFFFFFFFFu, acc[v].z, 16);
            acc[v].w += __shfl_xor_sync(0xFFFFFFFFu, acc[v].w, 16);
        }
        if (sub == 0) {
            const float inv = g_inv[n];
            const float4* self = reinterpret_cast<const float4*>(x + (size_t)n * F) + cl * VPL;
#pragma unroll
            for (int v = 0; v < VPL; v++) {
                float4 sv = self[v];
                float4 o;
                o.x = acc[v].x * inv + sv.x;
                o.y = acc[v].y * inv + sv.y;
                o.z = acc[v].z * inv + sv.z;
                o.w = acc[v].w * inv + sv.w;
                reinterpret_cast<float4*>(h + (size_t)n * F)[cl * VPL + v] = o;
            }
        }
    }
}

// ---------------------------------------------------------------------------
// pure GEMM phase with packed f32x2 FMA: y[n] = relu(h[n] @ W^T + b)
// W^T in smem; h rows via warp-uniform broadcast LDG.
// Thread tile: 4 neurons x 4 nodes; neuron dim packed into 2 f32x2 accums.
// ---------------------------------------------------------------------------
template <int F_IN, int F_OUT>
__device__ __forceinline__ void gemm_phase(const float* __restrict__ h,
                                           const float* __restrict__ W,
                                           const float* __restrict__ b,
                                           float* __restrict__ y,
                                           unsigned nb, float* sm) {
    constexpr int NQ = F_OUT / 4;
    constexpr int MQ = 256 / NQ;
    constexpr int BN = MQ * 4;
    constexpr int NG = (N_NODES + BN - 1) / BN;

    float* sWt = sm;                            // F_IN * F_OUT (transposed)
    const int t = threadIdx.x;
    __syncthreads();
    for (int i = t; i < F_IN * F_OUT; i += 256) {
        int r = i % F_OUT;
        int c = i / F_OUT;
        sWt[i] = __ldg(&W[r * F_IN + c]);
    }
    const int nq = t % NQ;
    const int mq = t / NQ;
    const float4 bv = __ldg(reinterpret_cast<const float4*>(b) + nq);
    const unsigned long long b01 = pk2(bv.x, bv.y);
    const unsigned long long b23 = pk2(bv.z, bv.w);
    const float4* wt4 = reinterpret_cast<const float4*>(sWt);
    __syncthreads();

    for (int g = blockIdx.x; g < NG; g += nb) {
        const int node0 = g * BN;
        const float* hr[4];
#pragma unroll
        for (int i = 0; i < 4; i++) {
            int n = node0 + mq * 4 + i;
            hr[i] = h + (size_t)((n < N_NODES) ? n : 0) * F_IN;
        }

        unsigned long long a01[4], a23[4];
#pragma unroll
        for (int i = 0; i < 4; i++) { a01[i] = b01; a23[i] = b23; }

#pragma unroll 4
        for (int k0 = 0; k0 < F_IN; k0 += 4) {
            float4 vv[4];
#pragma unroll
            for (int i = 0; i < 4; i++)
                vv[i] = __ldg(reinterpret_cast<const float4*>(hr[i] + k0));
#pragma unroll
            for (int j = 0; j < 4; j++) {
                float4 w = wt4[(size_t)(k0 + j) * NQ + nq];
                unsigned long long w01 = pk2(w.x, w.y);
                unsigned long long w23 = pk2(w.z, w.w);
#pragma unroll
                for (int i = 0; i < 4; i++) {
                    float vj = (j == 0) ? vv[i].x : (j == 1) ? vv[i].y
                             : (j == 2) ? vv[i].z : vv[i].w;
                    unsigned long long v2 = pk2(vj, vj);
                    fma2(a01[i], v2, w01);
                    fma2(a23[i], v2, w23);
                }
            }
        }
#pragma unroll
        for (int i = 0; i < 4; i++) {
            int n = node0 + mq * 4 + i;
            if (n < N_NODES) {
                float2 r01 = upk2(a01[i]);
                float2 r23 = upk2(a23[i]);
                float4 o;
                o.x = fmaxf(r01.x, 0.f);
                o.y = fmaxf(r01.y, 0.f);
                o.z = fmaxf(r23.x, 0.f);
                o.w = fmaxf(r23.y, 0.f);
                *reinterpret_cast<float4*>(y + (size_t)n * F_OUT + nq * 4) = o;
            }
        }
    }
}

// ---------------------------------------------------------------------------
// heads phase: next_event(64) + classes(10); embeddings already in out.
// ---------------------------------------------------------------------------
__device__ __forceinline__ void heads_phase(const float* __restrict__ emb,
                                            const float* __restrict__ Wp,
                                            const float* __restrict__ bp,
                                            const float* __restrict__ Wc,
                                            const float* __restrict__ bc,
                                            float* __restrict__ out,
                                            unsigned nb, float* sm) {
    constexpr int F = 64, NH = 74, WP = F + 4, NG8 = N_NODES / 8;
    float* sW  = sm;
    float* sB  = sm + NH * WP;
    float* sIn = sB + 128;

    const int t = threadIdx.x;
    __syncthreads();
    for (int i = t; i < 64 * F; i += 256) sW[(i / F) * WP + (i % F)] = Wp[i];
    for (int i = t; i < 10 * F; i += 256) sW[(64 + i / F) * WP + (i % F)] = Wc[i];
    if (t < 64) sB[t] = bp[t];
    else if (t < NH) sB[t] = bc[t - 64];
    __syncthreads();

    const int sub = t >> 7;
    const int tt  = t & 127;

    for (int g = blockIdx.x; g < NG8; g += nb) {
        const int node0 = g * 8;
        for (int i = t; i < 8 * F; i += 256) sIn[i] = emb[(size_t)node0 * F + i];
        __syncthreads();

        if (tt < NH) {
            float acc[4];
#pragma unroll
            for (int bn = 0; bn < 4; bn++) acc[bn] = sB[tt];
            const float4* w4 = reinterpret_cast<const float4*>(sW + tt * WP);
#pragma unroll
            for (int k4 = 0; k4 < F / 4; k4++) {
                float4 w = w4[k4];
#pragma unroll
                for (int bn = 0; bn < 4; bn++) {
                    float4 v = reinterpret_cast<const float4*>(sIn + (sub * 4 + bn) * F)[k4];
                    acc[bn] += w.x * v.x + w.y * v.y + w.z * v.z + w.w * v.w;
                }
            }
#pragma unroll
            for (int bn = 0; bn < 4; bn++) {
                int n = node0 + sub * 4 + bn;
                if (tt < 64)
                    out[(size_t)N_NODES * 64 + (size_t)n * 64 + tt] = acc[bn];
                else
                    out[(size_t)N_NODES * 128 + (size_t)n * 10 + (tt - 64)] = acc[bn];
            }
        }
        __syncthreads();
    }
}

// ---------------------------------------------------------------------------
// the one kernel
// ---------------------------------------------------------------------------
__global__ void __launch_bounds__(256, 3)
k_mega(const float* __restrict__ x,
       const int* __restrict__ src, const int* __restrict__ dst,
       const float* __restrict__ W1, const float* __restrict__ b1,
       const float* __restrict__ W2, const float* __restrict__ b2,
       const float* __restrict__ W3, const float* __restrict__ b3,
       const float* __restrict__ Wp, const float* __restrict__ bp,
       const float* __restrict__ Wc, const float* __restrict__ bc,
       float* __restrict__ out) {
    extern __shared__ float sm[];
    const unsigned nb = gridDim.x;
    const int t = threadIdx.x;
    const int gtid = blockIdx.x * 256 + t;
    const int gstride = nb * 256;

    // P0: zero
    for (int i = gtid; i < N_NODES; i += gstride) { g_degi[i] = 0; g_cursor[i] = 0; }
    gbar(nb);
    // P1: count
    for (int e = gtid; e < N_EDGES; e += gstride) atomicAdd(&g_degi[dst[e]], 1);
    gbar(nb);
    // P2a: per-chunk exclusive scans + inverse degree
    for (int c = blockIdx.x; c < NCHUNK; c += nb) {
        int i = c * 256 + t;
        int d = (i < N_NODES) ? g_degi[i] : 0;
        int ex = block_exscan256(d);
        if (i < N_NODES) {
            g_off[i] = ex;
            g_inv[i] = 1.0f / fmaxf((float)d, 1.0f);
        }
        if (t == 255) g_chunksum[c] = ex + d;
    }
    gbar(nb);
    // P2b: scan chunk sums (block 0)
    if (blockIdx.x == 0) {
        int v = (t < NCHUNK) ? g_chunksum[t] : 0;
        int ex = block_exscan256(v);
        if (t < NCHUNK) g_chunkpre[t] = ex;
    }
    gbar(nb);
    // P3: fill CSR
    for (int e = gtid; e < N_EDGES; e += gstride) {
        int d = dst[e];
        int pos = atomicAdd(&g_cursor[d], 1);
        g_csr[g_off[d] + g_chunkpre[d >> 8] + pos] = src[e];
    }
    gbar(nb);

    // layer 1
    gather_phase<64>(x, g_bufB, nb);
    gbar(nb);
    gemm_phase<64, 128>(g_bufB, W1, b1, g_bufA, nb, sm);
    gbar(nb);
    // layer 2
    gather_phase<128>(g_bufA, g_bufB, nb);
    gbar(nb);
    gemm_phase<128, 128>(g_bufB, W2, b2, g_bufA, nb, sm);
    gbar(nb);
    // layer 3 (embeddings straight to out)
    gather_phase<128>(g_bufA, g_bufB, nb);
    gbar(nb);
    gemm_phase<128, 64>(g_bufB, W3, b3, out, nb, sm);
    gbar(nb);
    // heads (read embeddings from out)
    heads_phase(out, Wp, bp, Wc, bc, out, nb, sm);
}

// ---------------------------------------------------------------------------
extern "C" void kernel_launch(void* const* d_in, const int* in_sizes, int n_in,
                              void* d_out, int out_size) {
    const float* x  = (const float*)d_in[0];
    const int*   ei = (const int*)d_in[1];
    const int* src = ei;
    const int* dst = ei + N_EDGES;
    const float* W1 = (const float*)d_in[2];
    const float* b1 = (const float*)d_in[3];
    const float* W2 = (const float*)d_in[4];
    const float* b2 = (const float*)d_in[5];
    const float* W3 = (const float*)d_in[6];
    const float* b3 = (const float*)d_in[7];
    const float* Wp = (const float*)d_in[8];
    const float* bp = (const float*)d_in[9];
    const float* Wc = (const float*)d_in[10];
    const float* bc = (const float*)d_in[11];
    float* out = (float*)d_out;

    // smem: max phase = GEMM2 W tile = 128*128*4 = 65536
    constexpr int SMEM = 128 * 128 * 4;

    static int grid = 0;
    if (grid == 0) {
        cudaFuncSetAttribute(k_mega, cudaFuncAttributeMaxDynamicSharedMemorySize, SMEM);
        int dev = 0, sms = 0, occ = 0;
        cudaGetDevice(&dev);
        cudaDeviceGetAttribute(&sms, cudaDevAttrMultiProcessorCount, dev);
        cudaOccupancyMaxActiveBlocksPerMultiprocessor(&occ, k_mega, 256, SMEM);
        if (occ < 1) occ = 1;
        grid = sms * occ;
    }

    k_mega<<<grid, 256, SMEM>>>(x, src, dst, W1, b1, W2, b2, W3, b3,
                                Wp, bp, Wc, bc, out);
}

// round 11
// speedup vs baseline: 1.1056x; 1.0546x over previous
#include <cuda_runtime.h>
#include <cstdint>

#define N_NODES 50000
#define N_PAD   50176          // padded row count (multiple of 128)
#define N_EDGES 800000
#define NCHUNK  ((N_NODES + 255) / 256) // 196

// ---------------------------------------------------------------------------
// scratch (__device__ globals; no allocation allowed)
// ---------------------------------------------------------------------------
__device__ float g_bufA[(size_t)N_PAD * 128];
__device__ float g_bufB[(size_t)N_PAD * 128];
__device__ float g_inv [N_NODES];
__device__ int   g_degi[N_NODES];
__device__ int   g_cursor[N_NODES];
__device__ int   g_off [N_NODES];
__device__ int   g_csr [N_EDGES];
__device__ int   g_chunksum[256];
__device__ int   g_chunkpre[256];
__device__ unsigned g_cnt;
__device__ volatile unsigned g_gen;

// ---------------------------------------------------------------------------
// packed f32x2 helpers (Blackwell FFMA2 via PTX)
// ---------------------------------------------------------------------------
__device__ __forceinline__ unsigned long long pk2(float lo, float hi) {
    unsigned long long r;
    asm("mov.b64 %0, {%1, %2};" : "=l"(r) : "f"(lo), "f"(hi));
    return r;
}
__device__ __forceinline__ void fma2(unsigned long long& d,
                                     unsigned long long a, unsigned long long b) {
    asm("fma.rn.f32x2 %0, %1, %2, %0;" : "+l"(d) : "l"(a), "l"(b));
}
__device__ __forceinline__ float2 upk2(unsigned long long v) {
    float2 f;
    asm("mov.b64 {%0, %1}, %2;" : "=f"(f.x), "=f"(f.y) : "l"(v));
    return f;
}

// ---------------------------------------------------------------------------
// grid-wide barrier
// ---------------------------------------------------------------------------
__device__ __forceinline__ void gbar(unsigned nb) {
    __syncthreads();
    if (threadIdx.x == 0) {
        __threadfence();
        unsigned my = g_gen;
        if (atomicAdd(&g_cnt, 1u) == nb - 1u) {
            g_cnt = 0u;
            __threadfence();
            g_gen = my + 1u;
        } else {
            while (g_gen == my) __nanosleep(32);
        }
        __threadfence();
    }
    __syncthreads();
}

// block-wide exclusive scan of one int per thread (256 threads)
__device__ __forceinline__ int block_exscan256(int v) {
    __shared__ int ws[8];
    const int t = threadIdx.x, lane = t & 31, wid = t >> 5;
    int s = v;
#pragma unroll
    for (int d = 1; d < 32; d <<= 1) {
        int u = __shfl_up_sync(0xFFFFFFFFu, s, d);
        if (lane >= d) s += u;
    }
    __syncthreads();
    if (lane == 31) ws[wid] = s;
    __syncthreads();
    int wpre = 0;
#pragma unroll
    for (int k = 0; k < 8; k++) if (k < wid) wpre += ws[k];
    return s - v + wpre;
}

// ---------------------------------------------------------------------------
// gather phase: h[n] = mean-gather(x) + x[n]  (+ optional bias & relu epilogue)
// one warp per node; 16 lanes cover a row; sub selects 1 of 2 edges.
// ---------------------------------------------------------------------------
template <int F, bool EPI>
__device__ __forceinline__ void gather_phase(const float* __restrict__ x,
                                             float* __restrict__ h,
                                             const float* __restrict__ bias,
                                             unsigned nb) {
    constexpr int VPL = F / 64;
    const int t     = threadIdx.x;
    const int lane  = t & 31;
    const int sub   = lane >> 4;
    const int cl    = lane & 15;
    const int gw    = blockIdx.x * 8 + (t >> 5);
    const int nwarp = nb * 8;

    float4 bq[VPL];
    if (EPI) {
#pragma unroll
        for (int v = 0; v < VPL; v++)
            bq[v] = __ldg(reinterpret_cast<const float4*>(bias) + cl * VPL + v);
    }

    for (int n = gw; n < N_NODES; n += nwarp) {
        const int beg = g_off[n] + g_chunkpre[n >> 8];
        const int dg  = g_degi[n];

        float4 acc[VPL];
#pragma unroll
        for (int v = 0; v < VPL; v++) acc[v] = make_float4(0.f, 0.f, 0.f, 0.f);

        int j = 0;
#pragma unroll 4
        for (; j + 2 <= dg; j += 2) {
            int e = __ldg(&g_csr[beg + j + sub]);
            const float4* r = reinterpret_cast<const float4*>(x + (size_t)e * F) + cl * VPL;
#pragma unroll
            for (int v = 0; v < VPL; v++) {
                float4 a = r[v];
                acc[v].x += a.x; acc[v].y += a.y; acc[v].z += a.z; acc[v].w += a.w;
            }
        }
        if (j < dg && sub == 0) {
            int e = __ldg(&g_csr[beg + j]);
            const float4* r = reinterpret_cast<const float4*>(x + (size_t)e * F) + cl * VPL;
#pragma unroll
            for (int v = 0; v < VPL; v++) {
                float4 a = r[v];
                acc[v].x += a.x; acc[v].y += a.y; acc[v].z += a.z; acc[v].w += a.w;
            }
        }
#pragma unroll
        for (int v = 0; v < VPL; v++) {
            acc[v].x += __shfl_xor_sync(0xFFFFFFFFu, acc[v].x, 16);
            acc[v].y += __shfl_xor_sync(0xFFFFFFFFu, acc[v].y, 16);
            acc[v].z += __shfl_xor_sync(0xFFFFFFFFu, acc[v].z, 16);
            acc[v].w += __shfl_xor_sync(0xFFFFFFFFu, acc[v].w, 16);
        }
        if (sub == 0) {
            const float inv = g_inv[n];
            const float4* self = reinterpret_cast<const float4*>(x + (size_t)n * F) + cl * VPL;
#pragma unroll
            for (int v = 0; v < VPL; v++) {
                float4 sv = self[v];
                float4 o;
                o.x = acc[v].x * inv + sv.x;
                o.y = acc[v].y * inv + sv.y;
                o.z = acc[v].z * inv + sv.z;
                o.w = acc[v].w * inv + sv.w;
                if (EPI) {
                    o.x = fmaxf(o.x + bq[v].x, 0.f);
                    o.y = fmaxf(o.y + bq[v].y, 0.f);
                    o.z = fmaxf(o.z + bq[v].z, 0.f);
                    o.w = fmaxf(o.w + bq[v].w, 0.f);
                }
                reinterpret_cast<float4*>(h + (size_t)n * F)[cl * VPL + v] = o;
            }
        }
    }
}

// ---------------------------------------------------------------------------
// GEMM phase, 8 nodes x 4 neurons per thread, packed f32x2 FMA.
// W^T in smem; h rows via (near-)uniform broadcast LDG with immediate offsets
// (h buffers padded to N_PAD rows so no per-row clamping is needed on loads).
// ---------------------------------------------------------------------------
template <int F_IN, int F_OUT, bool RELU, bool BIAS>
__device__ __forceinline__ void gemm_phase8(const float* __restrict__ h,
                                            const float* __restrict__ W,
                                            const float* __restrict__ b,
                                            float* __restrict__ y,
                                            unsigned nb, float* sm) {
    constexpr int NQ = F_OUT / 4;              // 32 or 16
    constexpr int MQ = 256 / NQ;               // 8 or 16
    constexpr int BN = MQ * 8;                 // 64 or 128
    constexpr int NG = (N_NODES + BN - 1) / BN;

    float* sWt = sm;                            // F_IN * F_OUT (transposed)
    const int t = threadIdx.x;
    __syncthreads();
    for (int i = t; i < F_IN * F_OUT; i += 256) {
        int r = i % F_OUT;
        int c = i / F_OUT;
        sWt[i] = __ldg(&W[r * F_IN + c]);
    }
    const int nq = t % NQ;
    const int mq = t / NQ;
    unsigned long long b01 = 0ull, b23 = 0ull;
    if (BIAS) {
        const float4 bv = __ldg(reinterpret_cast<const float4*>(b) + nq);
        b01 = pk2(bv.x, bv.y);
        b23 = pk2(bv.z, bv.w);
    }
    const float4* wt4 = reinterpret_cast<const float4*>(sWt);
    __syncthreads();

    for (int g = blockIdx.x; g < NG; g += nb) {
        const int node0 = g * BN;
        const int r0 = node0 + mq * 8;
        const float* hp = h + (size_t)r0 * F_IN;

        unsigned long long a01[8], a23[8];
#pragma unroll
        for (int i = 0; i < 8; i++) { a01[i] = b01; a23[i] = b23; }

#pragma unroll 2
        for (int k0 = 0; k0 < F_IN; k0 += 4) {
            unsigned long long w01[4], w23[4];
#pragma unroll
            for (int j = 0; j < 4; j++) {
                float4 w = wt4[(size_t)(k0 + j) * NQ + nq];
                w01[j] = pk2(w.x, w.y);
                w23[j] = pk2(w.z, w.w);
            }
#pragma unroll
            for (int i = 0; i < 8; i++) {
                float4 v = __ldg(reinterpret_cast<const float4*>(hp + (size_t)i * F_IN + k0));
                unsigned long long vx = pk2(v.x, v.x);
                unsigned long long vy = pk2(v.y, v.y);
                unsigned long long vz = pk2(v.z, v.z);
                unsigned long long vw = pk2(v.w, v.w);
                fma2(a01[i], vx, w01[0]); fma2(a23[i], vx, w23[0]);
                fma2(a01[i], vy, w01[1]); fma2(a23[i], vy, w23[1]);
                fma2(a01[i], vz, w01[2]); fma2(a23[i], vz, w23[2]);
                fma2(a01[i], vw, w01[3]); fma2(a23[i], vw, w23[3]);
            }
        }
#pragma unroll
        for (int i = 0; i < 8; i++) {
            int n = r0 + i;
            if (n < N_NODES) {
                float2 r01 = upk2(a01[i]);
                float2 r23 = upk2(a23[i]);
                float4 o;
                if (RELU) {
                    o.x = fmaxf(r01.x, 0.f); o.y = fmaxf(r01.y, 0.f);
                    o.z = fmaxf(r23.x, 0.f); o.w = fmaxf(r23.y, 0.f);
                } else {
                    o.x = r01.x; o.y = r01.y; o.z = r23.x; o.w = r23.y;
                }
                *reinterpret_cast<float4*>(y + (size_t)n * F_OUT + nq * 4) = o;
            }
        }
    }
}

// ---------------------------------------------------------------------------
// heads phase: next_event(64) + classes(10); embeddings already in out.
// ---------------------------------------------------------------------------
__device__ __forceinline__ void heads_phase(const float* __restrict__ emb,
                                            const float* __restrict__ Wp,
                                            const float* __restrict__ bp,
                                            const float* __restrict__ Wc,
                                            const float* __restrict__ bc,
                                            float* __restrict__ out,
                                            unsigned nb, float* sm) {
    constexpr int F = 64, NH = 74, WP = F + 4, NG8 = N_NODES / 8;
    float* sW  = sm;
    float* sB  = sm + NH * WP;
    float* sIn = sB + 128;

    const int t = threadIdx.x;
    __syncthreads();
    for (int i = t; i < 64 * F; i += 256) sW[(i / F) * WP + (i % F)] = Wp[i];
    for (int i = t; i < 10 * F; i += 256) sW[(64 + i / F) * WP + (i % F)] = Wc[i];
    if (t < 64) sB[t] = bp[t];
    else if (t < NH) sB[t] = bc[t - 64];
    __syncthreads();

    const int sub = t >> 7;
    const int tt  = t & 127;

    for (int g = blockIdx.x; g < NG8; g += nb) {
        const int node0 = g * 8;
        for (int i = t; i < 8 * F; i += 256) sIn[i] = emb[(size_t)node0 * F + i];
        __syncthreads();

        if (tt < NH) {
            float acc[4];
#pragma unroll
            for (int bn = 0; bn < 4; bn++) acc[bn] = sB[tt];
            const float4* w4 = reinterpret_cast<const float4*>(sW + tt * WP);
#pragma unroll
            for (int k4 = 0; k4 < F / 4; k4++) {
                float4 w = w4[k4];
#pragma unroll
                for (int bn = 0; bn < 4; bn++) {
                    float4 v = reinterpret_cast<const float4*>(sIn + (sub * 4 + bn) * F)[k4];
                    acc[bn] += w.x * v.x + w.y * v.y + w.z * v.z + w.w * v.w;
                }
            }
#pragma unroll
            for (int bn = 0; bn < 4; bn++) {
                int n = node0 + sub * 4 + bn;
                if (tt < 64)
                    out[(size_t)N_NODES * 64 + (size_t)n * 64 + tt] = acc[bn];
                else
                    out[(size_t)N_NODES * 128 + (size_t)n * 10 + (tt - 64)] = acc[bn];
            }
        }
        __syncthreads();
    }
}

// ---------------------------------------------------------------------------
// the one kernel
// ---------------------------------------------------------------------------
__global__ void __launch_bounds__(256, 3)
k_mega(const float* __restrict__ x,
       const int* __restrict__ src, const int* __restrict__ dst,
       const float* __restrict__ W1, const float* __restrict__ b1,
       const float* __restrict__ W2, const float* __restrict__ b2,
       const float* __restrict__ W3, const float* __restrict__ b3,
       const float* __restrict__ Wp, const float* __restrict__ bp,
       const float* __restrict__ Wc, const float* __restrict__ bc,
       float* __restrict__ out) {
    extern __shared__ float sm[];
    const unsigned nb = gridDim.x;
    const int t = threadIdx.x;
    const int gtid = blockIdx.x * 256 + t;
    const int gstride = nb * 256;

    // P0: zero
    for (int i = gtid; i < N_NODES; i += gstride) { g_degi[i] = 0; g_cursor[i] = 0; }
    gbar(nb);
    // P1: count
    for (int e = gtid; e < N_EDGES; e += gstride) atomicAdd(&g_degi[dst[e]], 1);
    gbar(nb);
    // P2a: per-chunk exclusive scans + inverse degree
    for (int c = blockIdx.x; c < NCHUNK; c += nb) {
        int i = c * 256 + t;
        int d = (i < N_NODES) ? g_degi[i] : 0;
        int ex = block_exscan256(d);
        if (i < N_NODES) {
            g_off[i] = ex;
            g_inv[i] = 1.0f / fmaxf((float)d, 1.0f);
        }
        if (t == 255) g_chunksum[c] = ex + d;
    }
    gbar(nb);
    // P2b: scan chunk sums (block 0)
    if (blockIdx.x == 0) {
        int v = (t < NCHUNK) ? g_chunksum[t] : 0;
        int ex = block_exscan256(v);
        if (t < NCHUNK) g_chunkpre[t] = ex;
    }
    gbar(nb);
    // P3: fill CSR
    for (int e = gtid; e < N_EDGES; e += gstride) {
        int d = dst[e];
        int pos = atomicAdd(&g_cursor[d], 1);
        g_csr[g_off[d] + g_chunkpre[d >> 8] + pos] = src[e];
    }
    gbar(nb);

    // layer 1: gather(64) -> gemm 64->128 (relu)
    gather_phase<64, false>(x, g_bufB, nullptr, nb);
    gbar(nb);
    gemm_phase8<64, 128, true, true>(g_bufB, W1, b1, g_bufA, nb, sm);
    gbar(nb);
    // layer 2: gather(128) -> gemm 128->128 (relu)
    gather_phase<128, false>(g_bufA, g_bufB, nullptr, nb);
    gbar(nb);
    gemm_phase8<128, 128, true, true>(g_bufB, W2, b2, g_bufA, nb, sm);
    gbar(nb);
    // layer 3 (commuted): z3 = y2 @ W3^T (no bias/relu), then 64-wide gather
    // with fused bias+relu epilogue writing embeddings straight to out.
    gemm_phase8<128, 64, false, false>(g_bufA, W3, nullptr, g_bufB, nb, sm);
    gbar(nb);
    gather_phase<64, true>(g_bufB, out, b3, nb);
    gbar(nb);
    // heads (read embeddings from out)
    heads_phase(out, Wp, bp, Wc, bc, out, nb, sm);
}

// ---------------------------------------------------------------------------
extern "C" void kernel_launch(void* const* d_in, const int* in_sizes, int n_in,
                              void* d_out, int out_size) {
    const float* x  = (const float*)d_in[0];
    const int*   ei = (const int*)d_in[1];
    const int* src = ei;
    const int* dst = ei + N_EDGES;
    const float* W1 = (const float*)d_in[2];
    const float* b1 = (const float*)d_in[3];
    const float* W2 = (const float*)d_in[4];
    const float* b2 = (const float*)d_in[5];
    const float* W3 = (const float*)d_in[6];
    const float* b3 = (const float*)d_in[7];
    const float* Wp = (const float*)d_in[8];
    const float* bp = (const float*)d_in[9];
    const float* Wc = (const float*)d_in[10];
    const float* bc = (const float*)d_in[11];
    float* out = (float*)d_out;

    // smem: max phase = GEMM2 W tile = 128*128*4 = 65536
    constexpr int SMEM = 128 * 128 * 4;

    static int grid = 0;
    if (grid == 0) {
        cudaFuncSetAttribute(k_mega, cudaFuncAttributeMaxDynamicSharedMemorySize, SMEM);
        int dev = 0, sms = 0, occ = 0;
        cudaGetDevice(&dev);
        cudaDeviceGetAttribute(&sms, cudaDevAttrMultiProcessorCount, dev);
        cudaOccupancyMaxActiveBlocksPerMultiprocessor(&occ, k_mega, 256, SMEM);
        if (occ < 1) occ = 1;
        grid = sms * occ;
    }

    k_mega<<<grid, 256, SMEM>>>(x, src, dst, W1, b1, W2, b2, W3, b3,
                                Wp, bp, Wc, bc, out);
}